// round 1
// baseline (speedup 1.0000x reference)
#include <cuda_runtime.h>

#define B 8
#define E 2000
#define NT 10000
#define NRELS 25
#define KT 16
#define TT 3
#define LL 32

// ---------------- scratch (device globals; no allocs allowed) ----------------
__device__ int   g_heads[NT];
__device__ int   g_tails[NT];
__device__ int   g_rels[NT];
__device__ int   g_ent[B];
__device__ int   g_tidx[E];
__device__ float g_ebase[E * 24];        // hidden_base indicator [E][24]
__device__ float g_bflag[B * NRELS];     // hx_raw indicator [B][25]
__device__ float g_wp[TT * LL * NRELS];  // softmax(w[t]) [t][l][r]
__device__ float g_tanhw[LL];
__device__ float g_hidx[B * LL];         // hidden_x at t=0
__device__ float g_hidden[TT * E * LL];  // hidden gates, layout [t][e][l]
__device__ float g_r0[E * B * LL];       // s ping buffer, layout [e][b][l]
__device__ float g_r1[E * B * LL];       // s pong buffer

__device__ __forceinline__ float clip01(float x) { return fminf(fmaxf(x, 0.f), 1.f); }

// ---------------- zero scratch ----------------
__global__ void k_init() {
    int st = gridDim.x * blockDim.x, i0 = blockIdx.x * blockDim.x + threadIdx.x;
    for (int i = i0; i < E * B * LL; i += st) { g_r0[i] = 0.f; g_r1[i] = 0.f; }
    for (int i = i0; i < E * 24;     i += st) g_ebase[i] = 0.f;
    for (int i = i0; i < B * NRELS;  i += st) g_bflag[i] = 0.f;
}

// ---------------- index extraction (the 160MB scan; HBM-bound) ----------------
__global__ void k_extract(const float* __restrict__ inx, const float* __restrict__ tmat,
                          const float4* __restrict__ e2t, const float4* __restrict__ t2e,
                          const float* __restrict__ t2r) {
    int st = gridDim.x * blockDim.x, i0 = blockIdx.x * blockDim.x + threadIdx.x;
    const int NE4 = E * NT / 4;   // 5M float4 each
    // e2triple [E][NT]: nonzero at (heads[n], n). NT % 4 == 0 so float4 stays in-row.
    for (int i = i0; i < NE4; i += st) {
        float4 v = e2t[i];
        if (v.x != 0.f || v.y != 0.f || v.z != 0.f || v.w != 0.f) {
            int idx = i * 4; int e = idx / NT; int n = idx - e * NT;
            if (v.x != 0.f) g_heads[n]     = e;
            if (v.y != 0.f) g_heads[n + 1] = e;
            if (v.z != 0.f) g_heads[n + 2] = e;
            if (v.w != 0.f) g_heads[n + 3] = e;
        }
    }
    // triple2e [NT][E]: nonzero at (n, tails[n]). E % 4 == 0.
    for (int i = i0; i < NE4; i += st) {
        float4 v = t2e[i];
        if (v.x != 0.f || v.y != 0.f || v.z != 0.f || v.w != 0.f) {
            int idx = i * 4; int n = idx / E; int e = idx - n * E;
            if (v.x != 0.f) g_tails[n] = e;
            if (v.y != 0.f) g_tails[n] = e + 1;
            if (v.z != 0.f) g_tails[n] = e + 2;
            if (v.w != 0.f) g_tails[n] = e + 3;
        }
    }
    for (int i = i0; i < NT * NRELS; i += st)
        if (t2r[i] != 0.f) g_rels[i / NRELS] = i % NRELS;
    for (int i = i0; i < E * KT; i += st)
        if (tmat[i] != 0.f) g_tidx[i / KT] = i % KT;
    for (int i = i0; i < B * E; i += st)
        if (inx[i] != 0.f) g_ent[i / E] = i % E;
}

// ---------------- indicator flags ----------------
__global__ void k_flags() {
    int n = blockIdx.x * blockDim.x + threadIdx.x;
    if (n >= NT) return;
    int r = g_rels[n], tl = g_tails[n], hd = g_heads[n];
    if (r < NRELS - 1) g_ebase[tl * 24 + r] = 1.f;
#pragma unroll
    for (int b = 0; b < B; b++)
        if (hd == g_ent[b]) g_bflag[b * NRELS + r] = 1.f;
}

// ---------------- small params: softmax, tanh(weight), hidden_x(t=0) ----------------
__global__ void k_small(const float* __restrict__ w, const float* __restrict__ weight,
                        const float* __restrict__ hx, const float* __restrict__ hxtype,
                        const float* __restrict__ alpha, const float* __restrict__ beta,
                        const float* __restrict__ alphax, const float* __restrict__ betax) {
    int i = threadIdx.x;
    if (i < TT * LL) {  // softmax rows of w: [t*L + l][25]
        float vals[NRELS]; float m = -1e30f;
        for (int r = 0; r < NRELS; r++) { vals[r] = w[i * NRELS + r]; m = fmaxf(m, vals[r]); }
        float s = 0.f;
        for (int r = 0; r < NRELS; r++) { vals[r] = expf(vals[r] - m); s += vals[r]; }
        float inv = 1.f / s;
        for (int r = 0; r < NRELS; r++) g_wp[i * NRELS + r] = vals[r] * inv;
    }
    if (i < LL) g_tanhw[i] = tanhf(weight[i]);
    if (i < B * LL) {   // hidden_x at t=0 (the only step where it is used)
        int b = i / LL, l = i % LL;
        float a0 = clip01(alpha[l] / 10.f), b0 = clip01(beta[l] / 10.f);
        int k = g_tidx[g_ent[b]];
        float htx = clip01(hxtype[l * KT + k] / 10.f);
        float acc = 0.f;
#pragma unroll
        for (int j = 0; j < 24; j++) {
            int src = (j < 12) ? (j + 12) : (j - 12);   // concat(hx_raw[:,12:24], hx_raw[:,0:12])
            acc += g_bflag[b * NRELS + src] * clip01(hx[l * 24 + j] / 10.f);
        }
        float gate = 1.f - clip01(clip01(alphax[l] / 10.f) + clip01(betax[l] / 10.f));
        g_hidx[i] = clip01(a0 * htx + b0 * acc) + gate;
    }
}

// ---------------- hidden[t][e][l] gates ----------------
__global__ void k_hidden(const float* __restrict__ h, const float* __restrict__ htype,
                         const float* __restrict__ alpha, const float* __restrict__ beta) {
    int z = blockIdx.x * blockDim.x + threadIdx.x;
    if (z >= TT * E * LL) return;
    int l = z & 31; int rest = z >> 5; int e = rest % E; int t = rest / E;
    float a  = clip01(alpha[t * LL + l] / 10.f);
    float bb = clip01(beta[t * LL + l] / 10.f);
    int k = g_tidx[e];
    float htp = clip01(htype[(t * LL + l) * KT + k] / 10.f);
    float acc = 0.f;
#pragma unroll
    for (int j = 0; j < 24; j++)
        acc += g_ebase[e * 24 + j] * clip01(h[(t * LL + l) * 24 + j] / 10.f);
    g_hidden[(t * E + e) * LL + l] = clip01(a * htp + bb * acc) + (1.f - clip01(a + bb));
}

// ---------------- t=0 propagation: r0[tails[n]][b][l] += wp0[l][rels[n]] if heads[n]==ent[b]
__global__ void k_prop0() {
    int st = gridDim.x * blockDim.x;
    for (int idx = blockIdx.x * blockDim.x + threadIdx.x; idx < NT * B * LL; idx += st) {
        int l = idx & 31; int q = idx >> 5; int b = q & 7; int n = q >> 3;
        if (g_heads[n] != g_ent[b]) continue;
        atomicAdd(&g_r0[(g_tails[n] * B + b) * LL + l], g_wp[l * NRELS + g_rels[n]]);
    }
}

// ---------------- t>0 propagation; hidden of the PREVIOUS step (+hidx at step 1)
//                  is applied at the read, since propagation is linear in s.
__global__ void k_prop(int step) {
    const float* src = (step == 1) ? g_r0 : g_r1;
    float*       dst = (step == 1) ? g_r1 : g_r0;
    const float* hid = g_hidden + (step - 1) * E * LL;
    const float* wp  = g_wp + step * LL * NRELS;
    int st = gridDim.x * blockDim.x;
    for (int idx = blockIdx.x * blockDim.x + threadIdx.x; idx < NT * B * LL; idx += st) {
        int l = idx & 31; int q = idx >> 5; int b = q & 7; int n = q >> 3;
        int hn = g_heads[n];
        float v = src[(hn * B + b) * LL + l];
        if (v == 0.f) continue;   // s is very sparse (support ~5·5^t entities per b)
        v *= hid[hn * LL + l] * wp[l * NRELS + g_rels[n]];
        if (step == 1) v *= g_hidx[b * LL + l];
        atomicAdd(&dst[(g_tails[n] * B + b) * LL + l], v);
    }
}

__global__ void k_zero_r0() {
    int st = gridDim.x * blockDim.x;
    for (int i = blockIdx.x * blockDim.x + threadIdx.x; i < E * B * LL; i += st) g_r0[i] = 0.f;
}

// ---------------- epilogue: out[b][e] = sum_l r_final·hidden2·tanh(weight[l])
__global__ void k_out(float* __restrict__ out) {
    int idx = blockIdx.x * blockDim.x + threadIdx.x;
    int l = idx & 31; int wrp = idx >> 5;
    if (wrp >= B * E) return;
    int e = wrp % E, b = wrp / E;
    float v = g_r0[(e * B + b) * LL + l] * g_hidden[(2 * E + e) * LL + l] * g_tanhw[l];
#pragma unroll
    for (int o = 16; o > 0; o >>= 1) v += __shfl_down_sync(0xffffffffu, v, o);
    if (l == 0) out[b * E + e] = v;
}

extern "C" void kernel_launch(void* const* d_in, const int* in_sizes, int n_in,
                              void* d_out, int out_size) {
    const float* inx    = (const float*)d_in[0];   // input_x   [8,2000]
    const float* tmat   = (const float*)d_in[1];   // type_mat  [2000,16]
    const float* e2t    = (const float*)d_in[2];   // e2triple  [2000,10000]
    const float* t2e    = (const float*)d_in[3];   // triple2e  [10000,2000]
    const float* t2r    = (const float*)d_in[4];   // triple2r  [10000,25]
    const float* w      = (const float*)d_in[5];   // [3,32,25]
    const float* weight = (const float*)d_in[6];   // [32,1]
    const float* h      = (const float*)d_in[7];   // [3,32,24]
    const float* hx     = (const float*)d_in[8];   // [32,24]
    const float* htype  = (const float*)d_in[9];   // [3,32,16]
    const float* hxtype = (const float*)d_in[10];  // [32,16]
    const float* alpha  = (const float*)d_in[11];  // [3,32]
    const float* beta   = (const float*)d_in[12];  // [3,32]
    const float* alphax = (const float*)d_in[13];  // [32]
    const float* betax  = (const float*)d_in[14];  // [32]
    float* out = (float*)d_out;

    k_init<<<512, 256>>>();
    k_extract<<<2048, 256>>>(inx, tmat, (const float4*)e2t, (const float4*)t2e, t2r);
    k_flags<<<(NT + 255) / 256, 256>>>();
    k_small<<<1, 512>>>(w, weight, hx, hxtype, alpha, beta, alphax, betax);
    k_hidden<<<(TT * E * LL + 255) / 256, 256>>>(h, htype, alpha, beta);
    k_prop0<<<2048, 256>>>();
    k_prop<<<2048, 256>>>(1);   // r0 -> r1, applies hidden0·hidden_x, wp1
    k_zero_r0<<<512, 256>>>();
    k_prop<<<2048, 256>>>(2);   // r1 -> r0, applies hidden1, wp2
    k_out<<<(B * E * 32 + 255) / 256, 256>>>(out);
}

// round 2
// speedup vs baseline: 1.0903x; 1.0903x over previous
#include <cuda_runtime.h>

#define B 8
#define E 2000
#define NT 10000
#define NRELS 25
#define KT 16
#define TT 3
#define LL 32

// ---------------- scratch (device globals; no allocs allowed) ----------------
__device__ int   g_heads[NT];
__device__ int   g_tails[NT];
__device__ int   g_rels[NT];
__device__ int   g_ent[B];
__device__ int   g_tidx[E];
__device__ float g_ebase[E * 24];        // hidden_base indicator [E][24]
__device__ float g_bflag[B * NRELS];     // hx_raw indicator [B][25]
__device__ float g_wp[TT * LL * NRELS];  // softmax(w[t]) [t][l][r]
__device__ float g_tanhw[LL];
__device__ float g_hidx[B * LL];         // hidden_x at t=0
__device__ float g_hidden[TT * E * LL];  // hidden gates, layout [t][e][l]
__device__ float g_r0[E * B * LL];       // s buffers, layout [e][b][l]
__device__ float g_r1[E * B * LL];
__device__ float g_r2[E * B * LL];

__device__ __forceinline__ float clip01(float x) { return fminf(fmaxf(x, 0.f), 1.f); }

// ------- extraction scan (160MB; HBM-bound) fused with scratch zeroing -------
__global__ void k_extract(const float* __restrict__ inx, const float* __restrict__ tmat,
                          const float4* __restrict__ e2t, const float4* __restrict__ t2e,
                          const float* __restrict__ t2r) {
    int st = gridDim.x * blockDim.x, i0 = blockIdx.x * blockDim.x + threadIdx.x;
    // zero scratch (disjoint from scan outputs; no ordering needed inside kernel)
    for (int i = i0; i < E * B * LL; i += st) { g_r0[i] = 0.f; g_r1[i] = 0.f; g_r2[i] = 0.f; }
    for (int i = i0; i < E * 24;     i += st) g_ebase[i] = 0.f;
    for (int i = i0; i < B * NRELS;  i += st) g_bflag[i] = 0.f;

    const int NE4 = E * NT / 4;   // 5M float4 each
    // e2triple [E][NT]: nonzero at (heads[n], n). NT % 4 == 0 so float4 stays in-row.
    for (int i = i0; i < NE4; i += st) {
        float4 v = e2t[i];
        if (v.x != 0.f || v.y != 0.f || v.z != 0.f || v.w != 0.f) {
            int idx = i * 4; int e = idx / NT; int n = idx - e * NT;
            if (v.x != 0.f) g_heads[n]     = e;
            if (v.y != 0.f) g_heads[n + 1] = e;
            if (v.z != 0.f) g_heads[n + 2] = e;
            if (v.w != 0.f) g_heads[n + 3] = e;
        }
    }
    // triple2e [NT][E]: nonzero at (n, tails[n]). E % 4 == 0.
    for (int i = i0; i < NE4; i += st) {
        float4 v = t2e[i];
        if (v.x != 0.f || v.y != 0.f || v.z != 0.f || v.w != 0.f) {
            int idx = i * 4; int n = idx / E; int e = idx - n * E;
            if (v.x != 0.f) g_tails[n] = e;
            if (v.y != 0.f) g_tails[n] = e + 1;
            if (v.z != 0.f) g_tails[n] = e + 2;
            if (v.w != 0.f) g_tails[n] = e + 3;
        }
    }
    for (int i = i0; i < NT * NRELS; i += st)
        if (t2r[i] != 0.f) g_rels[i / NRELS] = i % NRELS;
    for (int i = i0; i < E * KT; i += st)
        if (tmat[i] != 0.f) g_tidx[i / KT] = i % KT;
    for (int i = i0; i < B * E; i += st)
        if (inx[i] != 0.f) g_ent[i / E] = i % E;
}

// ---------------- indicator flags ----------------
__global__ void k_flags() {
    int n = blockIdx.x * blockDim.x + threadIdx.x;
    if (n >= NT) return;
    int r = g_rels[n], tl = g_tails[n], hd = g_heads[n];
    if (r < NRELS - 1) g_ebase[tl * 24 + r] = 1.f;
#pragma unroll
    for (int b = 0; b < B; b++)
        if (hd == g_ent[b]) g_bflag[b * NRELS + r] = 1.f;
}

// -------- gates: hidden[t][e][l] (blocks < HB) + small params (last block) --------
#define HB ((TT * E * LL + 255) / 256)   // 750 blocks of hidden work
__global__ void k_gates(const float* __restrict__ h, const float* __restrict__ htype,
                        const float* __restrict__ alpha, const float* __restrict__ beta,
                        const float* __restrict__ w, const float* __restrict__ weight,
                        const float* __restrict__ hx, const float* __restrict__ hxtype,
                        const float* __restrict__ alphax, const float* __restrict__ betax) {
    if (blockIdx.x < HB) {
        int z = blockIdx.x * 256 + threadIdx.x;
        if (z >= TT * E * LL) return;
        int l = z & 31; int rest = z >> 5; int e = rest % E; int t = rest / E;
        float a  = clip01(alpha[t * LL + l] * 0.1f);
        float bb = clip01(beta[t * LL + l] * 0.1f);
        int k = g_tidx[e];
        float htp = clip01(htype[(t * LL + l) * KT + k] * 0.1f);
        float acc = 0.f;
#pragma unroll
        for (int j = 0; j < 24; j++)
            acc += g_ebase[e * 24 + j] * clip01(h[(t * LL + l) * 24 + j] * 0.1f);
        g_hidden[(t * E + e) * LL + l] = clip01(a * htp + bb * acc) + (1.f - clip01(a + bb));
        return;
    }
    // last block: softmax rows, tanh(weight), hidden_x(t=0)
    int i = threadIdx.x;
    if (i < TT * LL) {          // softmax of w[t][l][:25]
        float vals[NRELS]; float m = -1e30f;
#pragma unroll
        for (int r = 0; r < NRELS; r++) { vals[r] = w[i * NRELS + r]; m = fmaxf(m, vals[r]); }
        float s = 0.f;
#pragma unroll
        for (int r = 0; r < NRELS; r++) { vals[r] = __expf(vals[r] - m); s += vals[r]; }
        float inv = __frcp_rn(s);
#pragma unroll
        for (int r = 0; r < NRELS; r++) g_wp[i * NRELS + r] = vals[r] * inv;
    }
    if (i < LL) g_tanhw[i] = tanhf(weight[i]);
    if (i < B * LL) {           // hidden_x at t=0 (only step where it is used)
        int b = i / LL, l = i % LL;
        float a0 = clip01(alpha[l] * 0.1f), b0 = clip01(beta[l] * 0.1f);
        int k = g_tidx[g_ent[b]];
        float htx = clip01(hxtype[l * KT + k] * 0.1f);
        float acc = 0.f;
#pragma unroll
        for (int j = 0; j < 24; j++) {
            int src = (j < 12) ? (j + 12) : (j - 12);  // concat(hx_raw[:,12:24], hx_raw[:,0:12])
            acc += g_bflag[b * NRELS + src] * clip01(hx[l * 24 + j] * 0.1f);
        }
        float gate = 1.f - clip01(clip01(alphax[l] * 0.1f) + clip01(betax[l] * 0.1f));
        g_hidx[i] = clip01(a0 * htx + b0 * acc) + gate;
    }
}

// ------- t=0: r0[tails[n]][b][l] += wp0[l][rels[n]] if heads[n]==ent[b] -------
__global__ void k_prop0() {
    int n = blockIdx.x; int b = threadIdx.x >> 5; int l = threadIdx.x & 31;
    if (g_heads[n] != g_ent[b]) return;
    atomicAdd(&g_r0[(g_tails[n] * B + b) * LL + l], g_wp[l * NRELS + g_rels[n]]);
}

// ------- t>0 propagation; previous step's hidden (+hidx at step 1) applied at
//         the read, since propagation is linear in s. One triple per block. -------
template <int STEP>
__global__ void k_prop() {
    const float* src = (STEP == 1) ? g_r0 : g_r1;
    float*       dst = (STEP == 1) ? g_r1 : g_r2;
    const float* hid = g_hidden + (STEP - 1) * E * LL;
    const float* wp  = g_wp + STEP * LL * NRELS;
    int n = blockIdx.x; int b = threadIdx.x >> 5; int l = threadIdx.x & 31;
    int hn = g_heads[n];
    float v = src[(hn * B + b) * LL + l];
    if (v == 0.f) return;        // s is very sparse
    v *= hid[hn * LL + l] * wp[l * NRELS + g_rels[n]];
    if (STEP == 1) v *= g_hidx[b * LL + l];
    atomicAdd(&dst[(g_tails[n] * B + b) * LL + l], v);
}

// ------- epilogue: out[b][e] = sum_l r2·hidden2·tanh(weight[l]) -------
__global__ void k_out(float* __restrict__ out) {
    int idx = blockIdx.x * blockDim.x + threadIdx.x;
    int l = idx & 31; int wrp = idx >> 5;
    if (wrp >= B * E) return;
    int e = wrp % E, b = wrp / E;
    float v = g_r2[(e * B + b) * LL + l] * g_hidden[(2 * E + e) * LL + l] * g_tanhw[l];
#pragma unroll
    for (int o = 16; o > 0; o >>= 1) v += __shfl_down_sync(0xffffffffu, v, o);
    if (l == 0) out[b * E + e] = v;
}

extern "C" void kernel_launch(void* const* d_in, const int* in_sizes, int n_in,
                              void* d_out, int out_size) {
    const float* inx    = (const float*)d_in[0];   // input_x   [8,2000]
    const float* tmat   = (const float*)d_in[1];   // type_mat  [2000,16]
    const float* e2t    = (const float*)d_in[2];   // e2triple  [2000,10000]
    const float* t2e    = (const float*)d_in[3];   // triple2e  [10000,2000]
    const float* t2r    = (const float*)d_in[4];   // triple2r  [10000,25]
    const float* w      = (const float*)d_in[5];   // [3,32,25]
    const float* weight = (const float*)d_in[6];   // [32,1]
    const float* h      = (const float*)d_in[7];   // [3,32,24]
    const float* hx     = (const float*)d_in[8];   // [32,24]
    const float* htype  = (const float*)d_in[9];   // [3,32,16]
    const float* hxtype = (const float*)d_in[10];  // [32,16]
    const float* alpha  = (const float*)d_in[11];  // [3,32]
    const float* beta   = (const float*)d_in[12];  // [3,32]
    const float* alphax = (const float*)d_in[13];  // [32]
    const float* betax  = (const float*)d_in[14];  // [32]
    float* out = (float*)d_out;

    k_extract<<<2048, 256>>>(inx, tmat, (const float4*)e2t, (const float4*)t2e, t2r);
    k_flags<<<(NT + 255) / 256, 256>>>();
    k_gates<<<HB + 1, 256>>>(h, htype, alpha, beta, w, weight, hx, hxtype, alphax, betax);
    k_prop0<<<NT, 256>>>();
    k_prop<1><<<NT, 256>>>();    // r0 -> r1, applies hidden0·hidden_x, wp1
    k_prop<2><<<NT, 256>>>();    // r1 -> r2, applies hidden1, wp2
    k_out<<<(B * E * 32 + 255) / 256, 256>>>(out);
}